// round 1
// baseline (speedup 1.0000x reference)
#include <cuda_runtime.h>
#include <cuda_bf16.h>
#include <math.h>

// Problem constants
#define BATCH 64
#define NATOM 512
#define DFEAT 128
#define DIMP  128
#define MROWS (BATCH * NATOM)      // 32768
#define NCOLS (2 * DIMP)           // 256 (Wq | Wk fused)

// GEMM tiling
#define BM 128
#define BN 128
#define BK 16
#define TM 8
#define TN 8

// Device scratch (allocation-free rule: static __device__ arrays)
__device__ float g_W[DFEAT * NCOLS];            // packed [128][256] = Wq | Wk
__device__ float g_bias[NCOLS];
__device__ float g_Q[(size_t)MROWS * DIMP];     // 16 MB
__device__ float g_K[(size_t)MROWS * DIMP];     // 16 MB

// ---------------------------------------------------------------------------
// Pack Wq|Wk into one [K=128, N=256] row-major matrix + bias vector
// ---------------------------------------------------------------------------
__global__ void pack_kernel(const float* __restrict__ Wq, const float* __restrict__ Wk,
                            const float* __restrict__ bq, const float* __restrict__ bk) {
    int idx = blockIdx.x * blockDim.x + threadIdx.x;      // 0 .. 16384
    if (idx < DFEAT * DIMP) {
        int k = idx / DIMP, n = idx % DIMP;
        g_W[k * NCOLS + n]        = Wq[idx];
        g_W[k * NCOLS + DIMP + n] = Wk[idx];
    }
    if (idx < DIMP) {
        g_bias[idx]        = bq[idx];
        g_bias[DIMP + idx] = bk[idx];
    }
}

// ---------------------------------------------------------------------------
// Fused projection GEMM: [32768x128] @ [128x256] -> writes g_Q / g_K
// Classic 128x128x16 block, 8x8 per-thread tile, 256 threads.
// ---------------------------------------------------------------------------
__global__ __launch_bounds__(256, 2)
void gemm_kernel(const float* __restrict__ A) {
    __shared__ float As[BK][BM];   // transposed A tile
    __shared__ float Bs[BK][BN];

    const int tid = threadIdx.x;
    const int gm  = blockIdx.x * BM;
    const int bn  = blockIdx.y * BN;          // 0 -> Q, 128 -> K
    const int tx  = tid & 15;                 // 0..15
    const int ty  = tid >> 4;                 // 0..15

    float acc[TM][TN];
    #pragma unroll
    for (int i = 0; i < TM; i++)
        #pragma unroll
        for (int j = 0; j < TN; j++) acc[i][j] = 0.0f;

    float bias_r[TN];
    #pragma unroll
    for (int j = 0; j < TN; j++) bias_r[j] = g_bias[bn + tx * TN + j];

    // A tile: 128 rows x 16 cols = 512 float4; thread loads f=tid and f=tid+256
    const int arow0 = tid >> 2,          acol0 = (tid & 3) * 4;
    const int arow1 = (tid + 256) >> 2,  acol1 = ((tid + 256) & 3) * 4;
    // B tile: 16 rows x 128 cols = 512 float4
    const int brow0 = tid >> 5,          bcol0 = (tid & 31) * 4;
    const int brow1 = (tid + 256) >> 5,  bcol1 = ((tid + 256) & 31) * 4;

    for (int k0 = 0; k0 < DFEAT; k0 += BK) {
        float4 a0 = *(const float4*)(A + (size_t)(gm + arow0) * DFEAT + k0 + acol0);
        float4 a1 = *(const float4*)(A + (size_t)(gm + arow1) * DFEAT + k0 + acol1);
        float4 b0 = *(const float4*)(g_W + (size_t)(k0 + brow0) * NCOLS + bn + bcol0);
        float4 b1 = *(const float4*)(g_W + (size_t)(k0 + brow1) * NCOLS + bn + bcol1);

        __syncthreads();   // previous iteration's compute must finish before overwrite
        As[acol0 + 0][arow0] = a0.x; As[acol0 + 1][arow0] = a0.y;
        As[acol0 + 2][arow0] = a0.z; As[acol0 + 3][arow0] = a0.w;
        As[acol1 + 0][arow1] = a1.x; As[acol1 + 1][arow1] = a1.y;
        As[acol1 + 2][arow1] = a1.z; As[acol1 + 3][arow1] = a1.w;
        *(float4*)&Bs[brow0][bcol0] = b0;
        *(float4*)&Bs[brow1][bcol1] = b1;
        __syncthreads();

        #pragma unroll
        for (int kk = 0; kk < BK; kk++) {
            float ar[TM], br[TN];
            #pragma unroll
            for (int i = 0; i < TM; i += 4) {
                float4 t = *(float4*)&As[kk][ty * TM + i];
                ar[i] = t.x; ar[i + 1] = t.y; ar[i + 2] = t.z; ar[i + 3] = t.w;
            }
            #pragma unroll
            for (int j = 0; j < TN; j += 4) {
                float4 t = *(float4*)&Bs[kk][tx * TN + j];
                br[j] = t.x; br[j + 1] = t.y; br[j + 2] = t.z; br[j + 3] = t.w;
            }
            #pragma unroll
            for (int i = 0; i < TM; i++)
                #pragma unroll
                for (int j = 0; j < TN; j++)
                    acc[i][j] += ar[i] * br[j];
        }
    }

    float* dst = (blockIdx.y == 0) ? g_Q : g_K;   // whole CTA targets one matrix
    #pragma unroll
    for (int i = 0; i < TM; i++) {
        const size_t row = (size_t)(gm + ty * TM + i);
        float4 v0, v1;
        v0.x = acc[i][0] + bias_r[0]; v0.y = acc[i][1] + bias_r[1];
        v0.z = acc[i][2] + bias_r[2]; v0.w = acc[i][3] + bias_r[3];
        v1.x = acc[i][4] + bias_r[4]; v1.y = acc[i][5] + bias_r[5];
        v1.z = acc[i][6] + bias_r[6]; v1.w = acc[i][7] + bias_r[7];
        *(float4*)(dst + row * DIMP + tx * TN)     = v0;
        *(float4*)(dst + row * DIMP + tx * TN + 4) = v1;
    }
}

// ---------------------------------------------------------------------------
// Block reductions (512 threads, 16 warps)
// ---------------------------------------------------------------------------
__device__ __forceinline__ float block_reduce_sum(float v, float* red) {
    int lane = threadIdx.x & 31, warp = threadIdx.x >> 5;
    #pragma unroll
    for (int o = 16; o; o >>= 1) v += __shfl_down_sync(0xffffffffu, v, o);
    if (lane == 0) red[warp] = v;
    __syncthreads();
    if (warp == 0) {
        v = (lane < 16) ? red[lane] : 0.0f;
        #pragma unroll
        for (int o = 8; o; o >>= 1) v += __shfl_down_sync(0xffffffffu, v, o);
        if (lane == 0) red[16] = v;
    }
    __syncthreads();
    float r = red[16];
    __syncthreads();
    return r;
}

__device__ __forceinline__ float block_reduce_max(float v, float* red) {
    int lane = threadIdx.x & 31, warp = threadIdx.x >> 5;
    #pragma unroll
    for (int o = 16; o; o >>= 1) v = fmaxf(v, __shfl_down_sync(0xffffffffu, v, o));
    if (lane == 0) red[warp] = v;
    __syncthreads();
    if (warp == 0) {
        v = (lane < 16) ? red[lane] : -INFINITY;
        #pragma unroll
        for (int o = 8; o; o >>= 1) v = fmaxf(v, __shfl_down_sync(0xffffffffu, v, o));
        if (lane == 0) red[16] = v;
    }
    __syncthreads();
    float r = red[16];
    __syncthreads();
    return r;
}

// ---------------------------------------------------------------------------
// Per-batch epilogue: q_sum -> agg -> normalize -> masked softmax -> context
// One CTA per batch, 512 threads (one per atom).
// ---------------------------------------------------------------------------
__global__ __launch_bounds__(512)
void attn_kernel(const float* __restrict__ mask, float* __restrict__ out) {
    const int b = blockIdx.x;
    const float* __restrict__ Kb = g_K + (size_t)b * NATOM * DIMP;
    const float* __restrict__ Qb = g_Q + (size_t)b * NATOM * DIMP;
    const float* __restrict__ m  = mask + (size_t)b * NATOM;

    __shared__ float qsum[DIMP];
    __shared__ float aggS[NATOM];
    __shared__ float attnS[NATOM];
    __shared__ float part4[4][DIMP];
    __shared__ float red[17];

    const int tid  = threadIdx.x;
    const int lane = tid & 31, warp = tid >> 5;
    const int d = tid & 127, p = tid >> 7;

    // --- q_sum[d] = sum_n mask[n]*q[n][d] (4 partial sums over n-quarters) ---
    {
        float acc = 0.0f;
        const int n0 = p * 128;
        #pragma unroll 4
        for (int n = n0; n < n0 + 128; n++)
            acc += m[n] * Qb[(size_t)n * DIMP + d];
        part4[p][d] = acc;
    }
    __syncthreads();
    if (tid < DIMP) qsum[tid] = part4[0][tid] + part4[1][tid] + part4[2][tid] + part4[3][tid];
    __syncthreads();

    // --- agg[n] = mask[n] * (k[n].q_sum - k[n].q[n]) ; one warp per 32 rows ---
    for (int r = 0; r < 32; r++) {
        const int n = warp * 32 + r;
        const float* kr = Kb + (size_t)n * DIMP;
        const float* qr = Qb + (size_t)n * DIMP;
        float s1 = 0.0f, s2 = 0.0f;
        #pragma unroll
        for (int dd = lane; dd < DIMP; dd += 32) {
            float kv = kr[dd];
            s1 += kv * qsum[dd];
            s2 += kv * qr[dd];
        }
        #pragma unroll
        for (int o = 16; o; o >>= 1) {
            s1 += __shfl_down_sync(0xffffffffu, s1, o);
            s2 += __shfl_down_sync(0xffffffffu, s2, o);
        }
        if (lane == 0) aggS[n] = m[n] * (s1 - s2);
    }
    __syncthreads();

    // --- euclidean normalize over atoms, masked softmax ---
    const float v = aggS[tid];
    const float total = block_reduce_sum(v * v, red);
    const float nrm = sqrtf(total);
    const float x = v / nrm + (1.0f - m[tid]) * (-1e9f);
    const float mx = block_reduce_max(x, red);
    const float e = expf(x - mx);
    const float denom = block_reduce_sum(e, red);
    const float attn = e / denom;
    out[(size_t)b * NATOM + tid] = attn;
    attnS[tid] = attn * m[tid];
    __syncthreads();

    // --- context[d] = sum_n mask[n]*attn[n]*k[n][d] ---
    {
        float acc = 0.0f;
        const int n0 = p * 128;
        #pragma unroll 4
        for (int n = n0; n < n0 + 128; n++)
            acc += attnS[n] * Kb[(size_t)n * DIMP + d];
        part4[p][d] = acc;
    }
    __syncthreads();
    if (tid < DIMP)
        out[(size_t)BATCH * NATOM + (size_t)b * DIMP + tid] =
            part4[0][tid] + part4[1][tid] + part4[2][tid] + part4[3][tid];
}

// ---------------------------------------------------------------------------
extern "C" void kernel_launch(void* const* d_in, const int* in_sizes, int n_in,
                              void* d_out, int out_size) {
    const float* atom_query = (const float*)d_in[0];
    const float* mask       = (const float*)d_in[1];
    const float* Wq         = (const float*)d_in[2];
    const float* bq         = (const float*)d_in[3];
    const float* Wk         = (const float*)d_in[4];
    const float* bk         = (const float*)d_in[5];
    float* out = (float*)d_out;

    pack_kernel<<<64, 256>>>(Wq, Wk, bq, bk);
    gemm_kernel<<<dim3(MROWS / BM, NCOLS / BN), 256>>>(atom_query);
    attn_kernel<<<BATCH, 512>>>(mask, out);
}